// round 2
// baseline (speedup 1.0000x reference)
#include <cuda_runtime.h>
#include <math.h>

// Problem constants
#define N1 400000
#define N2 400000
#define N3 800000
#define N4 1200000
#define U  128
#define BM 128
#define NTHR 256
#define PITCH 132   // float pitch for 128-wide smem tiles (float4-aligned)

// ---------------------------------------------------------------------------
// Scratch buffers (device globals: allocation-free per harness rules)
// ---------------------------------------------------------------------------
__device__ float g_H2 [(size_t)N2 * U];
__device__ float g_H3 [(size_t)N3 * U];
__device__ float g_H4 [(size_t)N4 * U];
__device__ float g_HD3[(size_t)N3 * U];
__device__ float g_H3D[(size_t)N3 * U];
__device__ float g_HD2[(size_t)N2 * U];
__device__ float g_H2D[(size_t)N2 * U];
__device__ float g_HD1[(size_t)N1 * U];

// ---------------------------------------------------------------------------
// Fused gather + MLP kernel:
//   out[r] = tanh( concat(segments(r)) @ W1 + b1 ) @ W2 + b2
// NSEG==3: segments = [ self[r], gat[idx[r,0]], gat[idx[r,1]] ]   (up pass)
// NSEG==2: segments = [ self[r], gat[r] ]                          (down pass)
// Block = 128 rows x 128 cols, 256 threads, 8x8 per-thread micro-tile.
// ---------------------------------------------------------------------------
template <int NSEG>
__global__ __launch_bounds__(NTHR, 1)
void mlp_kernel(const float* __restrict__ selfp,
                const float* __restrict__ gat,
                const int*   __restrict__ idx,
                const float* __restrict__ W1,   // [NSEG*U, U] row-major
                const float* __restrict__ b1,   // [U]
                const float* __restrict__ W2,   // [U, U] row-major
                const float* __restrict__ b2,   // [U]
                float* __restrict__ out)        // [N, U]
{
    extern __shared__ float sm[];
    float* As = sm;                 // 128 x PITCH
    float* Bs = sm + BM * PITCH;    // 128 x PITCH

    const int t  = threadIdx.x;
    const int tx = t & 15;          // 16 col groups of 8
    const int ty = t >> 4;          // 16 row groups of 8
    const long r0 = (long)blockIdx.x * BM;

    float acc[8][8];
#pragma unroll
    for (int i = 0; i < 8; i++)
#pragma unroll
        for (int j = 0; j < 8; j++) acc[i][j] = 0.f;

    // ---- Phase 1: H = X @ W1, K-loop over NSEG segments of 128 ----
    for (int seg = 0; seg < NSEG; seg++) {
        // Load W1 segment tile -> Bs (128x128)
        {
            const float4* src = (const float4*)(W1 + (size_t)seg * U * U);
#pragma unroll
            for (int i = 0; i < 16; i++) {
                int s = t + i * NTHR;           // 0..4095 float4 slots
                int row = s >> 5, c4 = s & 31;
                *(float4*)&Bs[row * PITCH + c4 * 4] = src[row * 32 + c4];
            }
        }
        // Load gathered A tile -> As (128 rows x 128)
        {
#pragma unroll
            for (int i = 0; i < 16; i++) {
                int s = t + i * NTHR;
                int row = s >> 5, c4 = s & 31;
                const float* srow;
                if (NSEG == 3) {
                    if (seg == 0) srow = selfp + (r0 + row) * U;
                    else          srow = gat + (long)idx[(r0 + row) * 2 + (seg - 1)] * U;
                } else {
                    srow = (seg == 0 ? selfp : gat) + (r0 + row) * U;
                }
                *(float4*)&As[row * PITCH + c4 * 4] = ((const float4*)srow)[c4];
            }
        }
        __syncthreads();
#pragma unroll 4
        for (int k = 0; k < U; k++) {
            float a[8], b[8];
#pragma unroll
            for (int i = 0; i < 8; i++) a[i] = As[(ty * 8 + i) * PITCH + k];
            float4 bv0 = *(const float4*)&Bs[k * PITCH + tx * 8];
            float4 bv1 = *(const float4*)&Bs[k * PITCH + tx * 8 + 4];
            b[0] = bv0.x; b[1] = bv0.y; b[2] = bv0.z; b[3] = bv0.w;
            b[4] = bv1.x; b[5] = bv1.y; b[6] = bv1.z; b[7] = bv1.w;
#pragma unroll
            for (int i = 0; i < 8; i++)
#pragma unroll
                for (int j = 0; j < 8; j++)
                    acc[i][j] = fmaf(a[i], b[j], acc[i][j]);
        }
        __syncthreads();
    }

    // ---- bias1 + tanh -> As (reused as H); load W2 -> Bs ----
    {
        const float4* src = (const float4*)W2;
#pragma unroll
        for (int i = 0; i < 16; i++) {
            int s = t + i * NTHR;
            int row = s >> 5, c4 = s & 31;
            *(float4*)&Bs[row * PITCH + c4 * 4] = src[row * 32 + c4];
        }
    }
    {
        float bias[8];
#pragma unroll
        for (int j = 0; j < 8; j++) bias[j] = b1[tx * 8 + j];
#pragma unroll
        for (int i = 0; i < 8; i++)
#pragma unroll
            for (int j = 0; j < 8; j++) {
                As[(ty * 8 + i) * PITCH + tx * 8 + j] = tanhf(acc[i][j] + bias[j]);
                acc[i][j] = 0.f;
            }
    }
    __syncthreads();

    // ---- Phase 2: Y = H @ W2 ----
#pragma unroll 4
    for (int k = 0; k < U; k++) {
        float a[8], b[8];
#pragma unroll
        for (int i = 0; i < 8; i++) a[i] = As[(ty * 8 + i) * PITCH + k];
        float4 bv0 = *(const float4*)&Bs[k * PITCH + tx * 8];
        float4 bv1 = *(const float4*)&Bs[k * PITCH + tx * 8 + 4];
        b[0] = bv0.x; b[1] = bv0.y; b[2] = bv0.z; b[3] = bv0.w;
        b[4] = bv1.x; b[5] = bv1.y; b[6] = bv1.z; b[7] = bv1.w;
#pragma unroll
        for (int i = 0; i < 8; i++)
#pragma unroll
            for (int j = 0; j < 8; j++)
                acc[i][j] = fmaf(a[i], b[j], acc[i][j]);
    }

    // ---- bias2 + store ----
    {
        float bias[8];
#pragma unroll
        for (int j = 0; j < 8; j++) bias[j] = b2[tx * 8 + j];
#pragma unroll
        for (int i = 0; i < 8; i++) {
            float4 v0 = make_float4(acc[i][0] + bias[0], acc[i][1] + bias[1],
                                    acc[i][2] + bias[2], acc[i][3] + bias[3]);
            float4 v1 = make_float4(acc[i][4] + bias[4], acc[i][5] + bias[5],
                                    acc[i][6] + bias[6], acc[i][7] + bias[7]);
            float* orow = out + (r0 + ty * 8 + i) * U + tx * 8;
            *(float4*)orow       = v0;
            *(float4*)(orow + 4) = v1;
        }
    }
}

// ---------------------------------------------------------------------------
// Scatter-sum: dst[idx[r,0]] += src[r]; dst[idx[r,1]] += src[r]
// Vectorized fp32x4 reductions (sm_90+ red.global.add.v4.f32).
// ---------------------------------------------------------------------------
__device__ __forceinline__ void red_add_v4(float* p, float4 v) {
    asm volatile("red.global.add.v4.f32 [%0], {%1,%2,%3,%4};"
                 :: "l"(p), "f"(v.x), "f"(v.y), "f"(v.z), "f"(v.w)
                 : "memory");
}

__global__ void scatter2_kernel(const float* __restrict__ src,
                                const int*   __restrict__ idx,
                                float* __restrict__ dst, int n)
{
    long i = (long)blockIdx.x * blockDim.x + threadIdx.x;
    if (i >= (long)n * 32) return;
    long row = i >> 5;
    int  c4  = (int)(i & 31);
    float4 v = ((const float4*)src)[row * 32 + c4];
    long i0 = idx[row * 2 + 0];
    long i1 = idx[row * 2 + 1];
    red_add_v4(dst + i0 * U + c4 * 4, v);
    red_add_v4(dst + i1 * U + c4 * 4, v);
}

__global__ void zero_kernel(float4* __restrict__ p, long n4)
{
    long i = (long)blockIdx.x * blockDim.x + threadIdx.x;
    if (i < n4) p[i] = make_float4(0.f, 0.f, 0.f, 0.f);
}

// ---------------------------------------------------------------------------
// Launch sequence (graph-capturable: kernels only, default stream)
// ---------------------------------------------------------------------------
extern "C" void kernel_launch(void* const* d_in, const int* in_sizes, int n_in,
                              void* d_out, int out_size)
{
    const float* h1 = (const float*)d_in[0];
    const float* h2 = (const float*)d_in[1];
    const float* h3 = (const float*)d_in[2];
    const float* h4 = (const float*)d_in[3];
    const int* idx2 = (const int*)d_in[4];
    const int* idx3 = (const int*)d_in[5];
    const int* idx4 = (const int*)d_in[6];

    const float* up2W1 = (const float*)d_in[7],  *up2b1 = (const float*)d_in[8],
               * up2W2 = (const float*)d_in[9],  *up2b2 = (const float*)d_in[10];
    const float* up3W1 = (const float*)d_in[11], *up3b1 = (const float*)d_in[12],
               * up3W2 = (const float*)d_in[13], *up3b2 = (const float*)d_in[14];
    const float* up4W1 = (const float*)d_in[15], *up4b1 = (const float*)d_in[16],
               * up4W2 = (const float*)d_in[17], *up4b2 = (const float*)d_in[18];
    const float* dn1W1 = (const float*)d_in[19], *dn1b1 = (const float*)d_in[20],
               * dn1W2 = (const float*)d_in[21], *dn1b2 = (const float*)d_in[22];
    const float* dn2W1 = (const float*)d_in[23], *dn2b1 = (const float*)d_in[24],
               * dn2W2 = (const float*)d_in[25], *dn2b2 = (const float*)d_in[26];
    const float* dn3W1 = (const float*)d_in[27], *dn3b1 = (const float*)d_in[28],
               * dn3W2 = (const float*)d_in[29], *dn3b2 = (const float*)d_in[30];

    float* out = (float*)d_out;

    float *H2, *H3, *H4, *HD3, *H3D, *HD2, *H2D, *HD1;
    cudaGetSymbolAddress((void**)&H2,  g_H2);
    cudaGetSymbolAddress((void**)&H3,  g_H3);
    cudaGetSymbolAddress((void**)&H4,  g_H4);
    cudaGetSymbolAddress((void**)&HD3, g_HD3);
    cudaGetSymbolAddress((void**)&H3D, g_H3D);
    cudaGetSymbolAddress((void**)&HD2, g_HD2);
    cudaGetSymbolAddress((void**)&H2D, g_H2D);
    cudaGetSymbolAddress((void**)&HD1, g_HD1);

    const size_t SMEM = (size_t)2 * BM * PITCH * sizeof(float);  // 135168 B
    cudaFuncSetAttribute(mlp_kernel<3>, cudaFuncAttributeMaxDynamicSharedMemorySize, (int)SMEM);
    cudaFuncSetAttribute(mlp_kernel<2>, cudaFuncAttributeMaxDynamicSharedMemorySize, (int)SMEM);

    // ---- upward pass ----
    mlp_kernel<3><<<N2 / BM, NTHR, SMEM>>>(h2, h1, idx2, up2W1, up2b1, up2W2, up2b2, H2);
    mlp_kernel<3><<<N3 / BM, NTHR, SMEM>>>(h3, H2, idx3, up3W1, up3b1, up3W2, up3b2, H3);
    mlp_kernel<3><<<N4 / BM, NTHR, SMEM>>>(h4, H3, idx4, up4W1, up4b1, up4W2, up4b2, H4);

    // ---- downward pass ----
    {
        long n4 = (long)N3 * 32;
        zero_kernel<<<(int)((n4 + 255) / 256), 256>>>((float4*)HD3, n4);
        long tot = (long)N4 * 32;
        scatter2_kernel<<<(int)((tot + 255) / 256), 256>>>(H4, idx4, HD3, N4);
        mlp_kernel<2><<<N3 / BM, NTHR, SMEM>>>(H3, HD3, nullptr, dn3W1, dn3b1, dn3W2, dn3b2, H3D);
    }
    {
        long n4 = (long)N2 * 32;
        zero_kernel<<<(int)((n4 + 255) / 256), 256>>>((float4*)HD2, n4);
        long tot = (long)N3 * 32;
        scatter2_kernel<<<(int)((tot + 255) / 256), 256>>>(H3D, idx3, HD2, N3);
        mlp_kernel<2><<<N2 / BM, NTHR, SMEM>>>(H2, HD2, nullptr, dn2W1, dn2b1, dn2W2, dn2b2, H2D);
    }
    {
        long n4 = (long)N1 * 32;
        zero_kernel<<<(int)((n4 + 255) / 256), 256>>>((float4*)HD1, n4);
        long tot = (long)N2 * 32;
        scatter2_kernel<<<(int)((tot + 255) / 256), 256>>>(H2D, idx2, HD1, N2);
        mlp_kernel<2><<<N1 / BM, NTHR, SMEM>>>(h1, HD1, nullptr, dn1W1, dn1b1, dn1W2, dn1b2, out);
    }
}

// round 3
// speedup vs baseline: 1.0493x; 1.0493x over previous
#include <cuda_runtime.h>
#include <math.h>

// Problem constants
#define N1 400000
#define N2 400000
#define N3 800000
#define N4 1200000
#define U  128
#define BM 128
#define NTHR 256
#define PITCH 132   // float pitch for 128-wide smem tiles (float4-aligned)

// ---------------------------------------------------------------------------
// Scratch buffers (device globals: allocation-free per harness rules)
// ---------------------------------------------------------------------------
__device__ float g_H2 [(size_t)N2 * U];
__device__ float g_H3 [(size_t)N3 * U];
__device__ float g_H4 [(size_t)N4 * U];
__device__ float g_HD3[(size_t)N3 * U];
__device__ float g_H3D[(size_t)N3 * U];
__device__ float g_HD2[(size_t)N2 * U];
__device__ float g_H2D[(size_t)N2 * U];
__device__ float g_HD1[(size_t)N1 * U];

// ---------------------------------------------------------------------------
// Fused gather + MLP kernel:
//   out[r] = tanh( concat(segments(r)) @ W1 + b1 ) @ W2 + b2
// NSEG==3: segments = [ self[r], gat[idx[r,0]], gat[idx[r,1]] ]   (up pass)
// NSEG==2: segments = [ self[r], gat[r] ]                          (down pass)
// Block = 128 rows x 128 cols, 256 threads, 8x8 per-thread micro-tile.
// ---------------------------------------------------------------------------
template <int NSEG>
__global__ __launch_bounds__(NTHR, 1)
void mlp_kernel(const float* __restrict__ selfp,
                const float* __restrict__ gat,
                const int*   __restrict__ idx,
                const float* __restrict__ W1,   // [NSEG*U, U] row-major
                const float* __restrict__ b1,   // [U]
                const float* __restrict__ W2,   // [U, U] row-major
                const float* __restrict__ b2,   // [U]
                float* __restrict__ out)        // [N, U]
{
    extern __shared__ float sm[];
    float* As = sm;                 // 128 x PITCH
    float* Bs = sm + BM * PITCH;    // 128 x PITCH

    const int t  = threadIdx.x;
    const int tx = t & 15;          // 16 col groups of 8
    const int ty = t >> 4;          // 16 row groups of 8
    const long r0 = (long)blockIdx.x * BM;

    float acc[8][8];
#pragma unroll
    for (int i = 0; i < 8; i++)
#pragma unroll
        for (int j = 0; j < 8; j++) acc[i][j] = 0.f;

    // ---- Phase 1: H = X @ W1, K-loop over NSEG segments of 128 ----
    for (int seg = 0; seg < NSEG; seg++) {
        // Load W1 segment tile -> Bs (128x128)
        {
            const float4* src = (const float4*)(W1 + (size_t)seg * U * U);
#pragma unroll
            for (int i = 0; i < 16; i++) {
                int s = t + i * NTHR;           // 0..4095 float4 slots
                int row = s >> 5, c4 = s & 31;
                *(float4*)&Bs[row * PITCH + c4 * 4] = src[row * 32 + c4];
            }
        }
        // Load gathered A tile -> As (128 rows x 128)
        {
#pragma unroll
            for (int i = 0; i < 16; i++) {
                int s = t + i * NTHR;
                int row = s >> 5, c4 = s & 31;
                const float* srow;
                if (NSEG == 3) {
                    if (seg == 0) srow = selfp + (r0 + row) * U;
                    else          srow = gat + (long)idx[(r0 + row) * 2 + (seg - 1)] * U;
                } else {
                    srow = (seg == 0 ? selfp : gat) + (r0 + row) * U;
                }
                *(float4*)&As[row * PITCH + c4 * 4] = ((const float4*)srow)[c4];
            }
        }
        __syncthreads();
#pragma unroll 4
        for (int k = 0; k < U; k++) {
            float a[8], b[8];
#pragma unroll
            for (int i = 0; i < 8; i++) a[i] = As[(ty * 8 + i) * PITCH + k];
            float4 bv0 = *(const float4*)&Bs[k * PITCH + tx * 8];
            float4 bv1 = *(const float4*)&Bs[k * PITCH + tx * 8 + 4];
            b[0] = bv0.x; b[1] = bv0.y; b[2] = bv0.z; b[3] = bv0.w;
            b[4] = bv1.x; b[5] = bv1.y; b[6] = bv1.z; b[7] = bv1.w;
#pragma unroll
            for (int i = 0; i < 8; i++)
#pragma unroll
                for (int j = 0; j < 8; j++)
                    acc[i][j] = fmaf(a[i], b[j], acc[i][j]);
        }
        __syncthreads();
    }

    // ---- bias1 + tanh -> As (reused as H); load W2 -> Bs ----
    {
        const float4* src = (const float4*)W2;
#pragma unroll
        for (int i = 0; i < 16; i++) {
            int s = t + i * NTHR;
            int row = s >> 5, c4 = s & 31;
            *(float4*)&Bs[row * PITCH + c4 * 4] = src[row * 32 + c4];
        }
    }
    {
        float bias[8];
#pragma unroll
        for (int j = 0; j < 8; j++) bias[j] = b1[tx * 8 + j];
#pragma unroll
        for (int i = 0; i < 8; i++)
#pragma unroll
            for (int j = 0; j < 8; j++) {
                As[(ty * 8 + i) * PITCH + tx * 8 + j] = tanhf(acc[i][j] + bias[j]);
                acc[i][j] = 0.f;
            }
    }
    __syncthreads();

    // ---- Phase 2: Y = H @ W2 ----
#pragma unroll 4
    for (int k = 0; k < U; k++) {
        float a[8], b[8];
#pragma unroll
        for (int i = 0; i < 8; i++) a[i] = As[(ty * 8 + i) * PITCH + k];
        float4 bv0 = *(const float4*)&Bs[k * PITCH + tx * 8];
        float4 bv1 = *(const float4*)&Bs[k * PITCH + tx * 8 + 4];
        b[0] = bv0.x; b[1] = bv0.y; b[2] = bv0.z; b[3] = bv0.w;
        b[4] = bv1.x; b[5] = bv1.y; b[6] = bv1.z; b[7] = bv1.w;
#pragma unroll
        for (int i = 0; i < 8; i++)
#pragma unroll
            for (int j = 0; j < 8; j++)
                acc[i][j] = fmaf(a[i], b[j], acc[i][j]);
    }

    // ---- bias2 + store ----
    {
        float bias[8];
#pragma unroll
        for (int j = 0; j < 8; j++) bias[j] = b2[tx * 8 + j];
#pragma unroll
        for (int i = 0; i < 8; i++) {
            float4 v0 = make_float4(acc[i][0] + bias[0], acc[i][1] + bias[1],
                                    acc[i][2] + bias[2], acc[i][3] + bias[3]);
            float4 v1 = make_float4(acc[i][4] + bias[4], acc[i][5] + bias[5],
                                    acc[i][6] + bias[6], acc[i][7] + bias[7]);
            float* orow = out + (r0 + ty * 8 + i) * U + tx * 8;
            *(float4*)orow       = v0;
            *(float4*)(orow + 4) = v1;
        }
    }
}

// ---------------------------------------------------------------------------
// Scatter-sum: dst[idx[r,0]] += src[r]; dst[idx[r,1]] += src[r]
// Vectorized fp32x4 reductions (sm_90+ red.global.add.v4.f32).
// ---------------------------------------------------------------------------
__device__ __forceinline__ void red_add_v4(float* p, float4 v) {
    asm volatile("red.global.add.v4.f32 [%0], {%1,%2,%3,%4};"
                 :: "l"(p), "f"(v.x), "f"(v.y), "f"(v.z), "f"(v.w)
                 : "memory");
}

__global__ void scatter2_kernel(const float* __restrict__ src,
                                const int*   __restrict__ idx,
                                float* __restrict__ dst, int n)
{
    long i = (long)blockIdx.x * blockDim.x + threadIdx.x;
    if (i >= (long)n * 32) return;
    long row = i >> 5;
    int  c4  = (int)(i & 31);
    float4 v = ((const float4*)src)[row * 32 + c4];
    long i0 = idx[row * 2 + 0];
    long i1 = idx[row * 2 + 1];
    red_add_v4(dst + i0 * U + c4 * 4, v);
    red_add_v4(dst + i1 * U + c4 * 4, v);
}

__global__ void zero_kernel(float4* __restrict__ p, long n4)
{
    long i = (long)blockIdx.x * blockDim.x + threadIdx.x;
    if (i < n4) p[i] = make_float4(0.f, 0.f, 0.f, 0.f);
}

// ---------------------------------------------------------------------------
// Launch sequence (graph-capturable: kernels only, default stream)
// ---------------------------------------------------------------------------
extern "C" void kernel_launch(void* const* d_in, const int* in_sizes, int n_in,
                              void* d_out, int out_size)
{
    const float* h1 = (const float*)d_in[0];
    const float* h2 = (const float*)d_in[1];
    const float* h3 = (const float*)d_in[2];
    const float* h4 = (const float*)d_in[3];
    const int* idx2 = (const int*)d_in[4];
    const int* idx3 = (const int*)d_in[5];
    const int* idx4 = (const int*)d_in[6];

    const float* up2W1 = (const float*)d_in[7],  *up2b1 = (const float*)d_in[8],
               * up2W2 = (const float*)d_in[9],  *up2b2 = (const float*)d_in[10];
    const float* up3W1 = (const float*)d_in[11], *up3b1 = (const float*)d_in[12],
               * up3W2 = (const float*)d_in[13], *up3b2 = (const float*)d_in[14];
    const float* up4W1 = (const float*)d_in[15], *up4b1 = (const float*)d_in[16],
               * up4W2 = (const float*)d_in[17], *up4b2 = (const float*)d_in[18];
    const float* dn1W1 = (const float*)d_in[19], *dn1b1 = (const float*)d_in[20],
               * dn1W2 = (const float*)d_in[21], *dn1b2 = (const float*)d_in[22];
    const float* dn2W1 = (const float*)d_in[23], *dn2b1 = (const float*)d_in[24],
               * dn2W2 = (const float*)d_in[25], *dn2b2 = (const float*)d_in[26];
    const float* dn3W1 = (const float*)d_in[27], *dn3b1 = (const float*)d_in[28],
               * dn3W2 = (const float*)d_in[29], *dn3b2 = (const float*)d_in[30];

    float* out = (float*)d_out;

    float *H2, *H3, *H4, *HD3, *H3D, *HD2, *H2D, *HD1;
    cudaGetSymbolAddress((void**)&H2,  g_H2);
    cudaGetSymbolAddress((void**)&H3,  g_H3);
    cudaGetSymbolAddress((void**)&H4,  g_H4);
    cudaGetSymbolAddress((void**)&HD3, g_HD3);
    cudaGetSymbolAddress((void**)&H3D, g_H3D);
    cudaGetSymbolAddress((void**)&HD2, g_HD2);
    cudaGetSymbolAddress((void**)&H2D, g_H2D);
    cudaGetSymbolAddress((void**)&HD1, g_HD1);

    const size_t SMEM = (size_t)2 * BM * PITCH * sizeof(float);  // 135168 B
    cudaFuncSetAttribute(mlp_kernel<3>, cudaFuncAttributeMaxDynamicSharedMemorySize, (int)SMEM);
    cudaFuncSetAttribute(mlp_kernel<2>, cudaFuncAttributeMaxDynamicSharedMemorySize, (int)SMEM);

    // ---- upward pass ----
    mlp_kernel<3><<<N2 / BM, NTHR, SMEM>>>(h2, h1, idx2, up2W1, up2b1, up2W2, up2b2, H2);
    mlp_kernel<3><<<N3 / BM, NTHR, SMEM>>>(h3, H2, idx3, up3W1, up3b1, up3W2, up3b2, H3);
    mlp_kernel<3><<<N4 / BM, NTHR, SMEM>>>(h4, H3, idx4, up4W1, up4b1, up4W2, up4b2, H4);

    // ---- downward pass ----
    {
        long n4 = (long)N3 * 32;
        zero_kernel<<<(int)((n4 + 255) / 256), 256>>>((float4*)HD3, n4);
        long tot = (long)N4 * 32;
        scatter2_kernel<<<(int)((tot + 255) / 256), 256>>>(H4, idx4, HD3, N4);
        mlp_kernel<2><<<N3 / BM, NTHR, SMEM>>>(H3, HD3, nullptr, dn3W1, dn3b1, dn3W2, dn3b2, H3D);
    }
    {
        long n4 = (long)N2 * 32;
        zero_kernel<<<(int)((n4 + 255) / 256), 256>>>((float4*)HD2, n4);
        long tot = (long)N3 * 32;
        scatter2_kernel<<<(int)((tot + 255) / 256), 256>>>(H3D, idx3, HD2, N3);
        mlp_kernel<2><<<N2 / BM, NTHR, SMEM>>>(H2, HD2, nullptr, dn2W1, dn2b1, dn2W2, dn2b2, H2D);
    }
    {
        long n4 = (long)N1 * 32;
        zero_kernel<<<(int)((n4 + 255) / 256), 256>>>((float4*)HD1, n4);
        long tot = (long)N2 * 32;
        scatter2_kernel<<<(int)((tot + 255) / 256), 256>>>(H2D, idx2, HD1, N2);
        mlp_kernel<2><<<N1 / BM, NTHR, SMEM>>>(h1, HD1, nullptr, dn1W1, dn1b1, dn1W2, dn1b2, out);
    }
}

// round 4
// speedup vs baseline: 2.3490x; 2.2387x over previous
#include <cuda_runtime.h>
#include <math.h>
#include <stdint.h>

// Problem constants
#define N1 400000
#define N2 400000
#define N3 800000
#define N4 1200000
#define U  128
#define BM 128
#define NTHR 256
#define PITCH 132   // float pitch for 128-wide smem tiles

// ---------------------------------------------------------------------------
// Scratch buffers
// ---------------------------------------------------------------------------
__device__ float g_H2 [(size_t)N2 * U];
__device__ float g_H3 [(size_t)N3 * U];
__device__ float g_H4 [(size_t)N4 * U];
__device__ float g_HD3[(size_t)N3 * U];
__device__ float g_H3D[(size_t)N3 * U];
__device__ float g_HD2[(size_t)N2 * U];
__device__ float g_H2D[(size_t)N2 * U];
__device__ float g_HD1[(size_t)N1 * U];

// ---------------------------------------------------------------------------
// tf32 helpers
// ---------------------------------------------------------------------------
__device__ __forceinline__ float f2tf(float x) {
    uint32_t r;
    asm("cvt.rna.tf32.f32 %0, %1;" : "=r"(r) : "f"(x));
    return __uint_as_float(r);
}

__device__ __forceinline__ float4 f2tf4(float4 v) {
    v.x = f2tf(v.x); v.y = f2tf(v.y); v.z = f2tf(v.z); v.w = f2tf(v.w);
    return v;
}

__device__ __forceinline__ void mma_tf32(float c[4],
                                         uint32_t a0, uint32_t a1, uint32_t a2, uint32_t a3,
                                         uint32_t b0, uint32_t b1) {
    asm volatile(
        "mma.sync.aligned.m16n8k8.row.col.f32.tf32.tf32.f32 "
        "{%0,%1,%2,%3}, {%4,%5,%6,%7}, {%8,%9}, {%0,%1,%2,%3};"
        : "+f"(c[0]), "+f"(c[1]), "+f"(c[2]), "+f"(c[3])
        : "r"(a0), "r"(a1), "r"(a2), "r"(a3), "r"(b0), "r"(b1));
}

// ---------------------------------------------------------------------------
// Fused gather + MLP kernel (tf32 tensor cores):
//   out[r] = tanh( concat(segments(r)) @ W1 + b1 ) @ W2 + b2
// NSEG==3: segments = [ self[r], gat[idx[r,0]], gat[idx[r,1]] ]   (up pass)
// NSEG==2: segments = [ self[r], gat[r] ]                          (down pass)
// Block tile 128x128, 8 warps in a 4(m) x 2(n) grid; each warp 32x64 via
// 2x8 m16n8k8 tf32 HMMA tiles.
// ---------------------------------------------------------------------------
template <int NSEG>
__global__ __launch_bounds__(NTHR, 1)
void mlp_kernel(const float* __restrict__ selfp,
                const float* __restrict__ gat,
                const int*   __restrict__ idx,
                const float* __restrict__ W1,   // [NSEG*U, U] row-major
                const float* __restrict__ b1,   // [U]
                const float* __restrict__ W2,   // [U, U] row-major
                const float* __restrict__ b2,   // [U]
                float* __restrict__ out)        // [N, U]
{
    extern __shared__ float sm[];
    float* As = sm;                 // 128 x PITCH  (A tile / H tile)
    float* Bs = sm + BM * PITCH;    // 128 x PITCH  (W tile, k-major rows)

    const int t    = threadIdx.x;
    const int lane = t & 31;
    const int wid  = t >> 5;
    const int g    = lane >> 2;     // group id 0..7
    const int tg   = lane & 3;      // thread-in-group 0..3
    const int wm   = (wid & 3) * 32;  // warp m offset
    const int wn   = (wid >> 2) * 64; // warp n offset
    const long r0  = (long)blockIdx.x * BM;

    float acc[2][8][4];
#pragma unroll
    for (int mt = 0; mt < 2; mt++)
#pragma unroll
        for (int nt = 0; nt < 8; nt++)
#pragma unroll
            for (int c = 0; c < 4; c++) acc[mt][nt][c] = 0.f;

    // ---- Phase 1: H = X @ W1, looping over NSEG K-segments of 128 ----
    for (int seg = 0; seg < NSEG; seg++) {
        // W1 segment tile -> Bs (tf32-rounded)
        {
            const float4* src = (const float4*)(W1 + (size_t)seg * U * U);
#pragma unroll
            for (int i = 0; i < 16; i++) {
                int s = t + i * NTHR;
                int row = s >> 5, c4 = s & 31;
                *(float4*)&Bs[row * PITCH + c4 * 4] = f2tf4(src[row * 32 + c4]);
            }
        }
        // Gathered A tile -> As (tf32-rounded)
        {
#pragma unroll
            for (int i = 0; i < 16; i++) {
                int s = t + i * NTHR;
                int row = s >> 5, c4 = s & 31;
                const float* srow;
                if (NSEG == 3) {
                    if (seg == 0) srow = selfp + (r0 + row) * U;
                    else          srow = gat + (long)idx[(r0 + row) * 2 + (seg - 1)] * U;
                } else {
                    srow = (seg == 0 ? selfp : gat) + (r0 + row) * U;
                }
                *(float4*)&As[row * PITCH + c4 * 4] = f2tf4(((const float4*)srow)[c4]);
            }
        }
        __syncthreads();

#pragma unroll 2
        for (int k0 = 0; k0 < U; k0 += 8) {
            uint32_t a[2][4], b[8][2];
#pragma unroll
            for (int mt = 0; mt < 2; mt++) {
                const float* ab = As + (wm + mt * 16) * PITCH + k0;
                a[mt][0] = __float_as_uint(ab[(g    ) * PITCH + tg    ]);
                a[mt][1] = __float_as_uint(ab[(g + 8) * PITCH + tg    ]);
                a[mt][2] = __float_as_uint(ab[(g    ) * PITCH + tg + 4]);
                a[mt][3] = __float_as_uint(ab[(g + 8) * PITCH + tg + 4]);
            }
#pragma unroll
            for (int nt = 0; nt < 8; nt++) {
                const float* bb = Bs + k0 * PITCH + wn + nt * 8 + g;
                b[nt][0] = __float_as_uint(bb[(tg    ) * PITCH]);
                b[nt][1] = __float_as_uint(bb[(tg + 4) * PITCH]);
            }
#pragma unroll
            for (int mt = 0; mt < 2; mt++)
#pragma unroll
                for (int nt = 0; nt < 8; nt++)
                    mma_tf32(acc[mt][nt], a[mt][0], a[mt][1], a[mt][2], a[mt][3],
                             b[nt][0], b[nt][1]);
        }
        __syncthreads();
    }

    // ---- bias1 + tanh -> As (as H, tf32-rounded); W2 -> Bs ----
    {
        const float4* src = (const float4*)W2;
#pragma unroll
        for (int i = 0; i < 16; i++) {
            int s = t + i * NTHR;
            int row = s >> 5, c4 = s & 31;
            *(float4*)&Bs[row * PITCH + c4 * 4] = f2tf4(src[row * 32 + c4]);
        }
    }
#pragma unroll
    for (int nt = 0; nt < 8; nt++) {
        int col = wn + nt * 8 + 2 * tg;
        float bx = __ldg(&b1[col]), by = __ldg(&b1[col + 1]);
#pragma unroll
        for (int mt = 0; mt < 2; mt++) {
            int row0 = wm + mt * 16 + g;
            As[(row0    ) * PITCH + col    ] = f2tf(tanhf(acc[mt][nt][0] + bx));
            As[(row0    ) * PITCH + col + 1] = f2tf(tanhf(acc[mt][nt][1] + by));
            As[(row0 + 8) * PITCH + col    ] = f2tf(tanhf(acc[mt][nt][2] + bx));
            As[(row0 + 8) * PITCH + col + 1] = f2tf(tanhf(acc[mt][nt][3] + by));
            acc[mt][nt][0] = 0.f; acc[mt][nt][1] = 0.f;
            acc[mt][nt][2] = 0.f; acc[mt][nt][3] = 0.f;
        }
    }
    __syncthreads();

    // ---- Phase 2: Y = H @ W2 ----
#pragma unroll 2
    for (int k0 = 0; k0 < U; k0 += 8) {
        uint32_t a[2][4], b[8][2];
#pragma unroll
        for (int mt = 0; mt < 2; mt++) {
            const float* ab = As + (wm + mt * 16) * PITCH + k0;
            a[mt][0] = __float_as_uint(ab[(g    ) * PITCH + tg    ]);
            a[mt][1] = __float_as_uint(ab[(g + 8) * PITCH + tg    ]);
            a[mt][2] = __float_as_uint(ab[(g    ) * PITCH + tg + 4]);
            a[mt][3] = __float_as_uint(ab[(g + 8) * PITCH + tg + 4]);
        }
#pragma unroll
        for (int nt = 0; nt < 8; nt++) {
            const float* bb = Bs + k0 * PITCH + wn + nt * 8 + g;
            b[nt][0] = __float_as_uint(bb[(tg    ) * PITCH]);
            b[nt][1] = __float_as_uint(bb[(tg + 4) * PITCH]);
        }
#pragma unroll
        for (int mt = 0; mt < 2; mt++)
#pragma unroll
            for (int nt = 0; nt < 8; nt++)
                mma_tf32(acc[mt][nt], a[mt][0], a[mt][1], a[mt][2], a[mt][3],
                         b[nt][0], b[nt][1]);
    }

    // ---- bias2 + store ----
#pragma unroll
    for (int nt = 0; nt < 8; nt++) {
        int col = wn + nt * 8 + 2 * tg;
        float bx = __ldg(&b2[col]), by = __ldg(&b2[col + 1]);
#pragma unroll
        for (int mt = 0; mt < 2; mt++) {
            long row0 = r0 + wm + mt * 16 + g;
            *(float2*)&out[(row0    ) * U + col] =
                make_float2(acc[mt][nt][0] + bx, acc[mt][nt][1] + by);
            *(float2*)&out[(row0 + 8) * U + col] =
                make_float2(acc[mt][nt][2] + bx, acc[mt][nt][3] + by);
        }
    }
}

// ---------------------------------------------------------------------------
// Scatter-sum: dst[idx[r,0]] += src[r]; dst[idx[r,1]] += src[r]
// ---------------------------------------------------------------------------
__device__ __forceinline__ void red_add_v4(float* p, float4 v) {
    asm volatile("red.global.add.v4.f32 [%0], {%1,%2,%3,%4};"
                 :: "l"(p), "f"(v.x), "f"(v.y), "f"(v.z), "f"(v.w)
                 : "memory");
}

__global__ void scatter2_kernel(const float* __restrict__ src,
                                const int*   __restrict__ idx,
                                float* __restrict__ dst, int n)
{
    long i = (long)blockIdx.x * blockDim.x + threadIdx.x;
    if (i >= (long)n * 32) return;
    long row = i >> 5;
    int  c4  = (int)(i & 31);
    float4 v = ((const float4*)src)[row * 32 + c4];
    long i0 = idx[row * 2 + 0];
    long i1 = idx[row * 2 + 1];
    red_add_v4(dst + i0 * U + c4 * 4, v);
    red_add_v4(dst + i1 * U + c4 * 4, v);
}

__global__ void zero_kernel(float4* __restrict__ p, long n4)
{
    long i = (long)blockIdx.x * blockDim.x + threadIdx.x;
    if (i < n4) p[i] = make_float4(0.f, 0.f, 0.f, 0.f);
}

// ---------------------------------------------------------------------------
// Launch sequence
// ---------------------------------------------------------------------------
extern "C" void kernel_launch(void* const* d_in, const int* in_sizes, int n_in,
                              void* d_out, int out_size)
{
    const float* h1 = (const float*)d_in[0];
    const float* h2 = (const float*)d_in[1];
    const float* h3 = (const float*)d_in[2];
    const float* h4 = (const float*)d_in[3];
    const int* idx2 = (const int*)d_in[4];
    const int* idx3 = (const int*)d_in[5];
    const int* idx4 = (const int*)d_in[6];

    const float* up2W1 = (const float*)d_in[7],  *up2b1 = (const float*)d_in[8],
               * up2W2 = (const float*)d_in[9],  *up2b2 = (const float*)d_in[10];
    const float* up3W1 = (const float*)d_in[11], *up3b1 = (const float*)d_in[12],
               * up3W2 = (const float*)d_in[13], *up3b2 = (const float*)d_in[14];
    const float* up4W1 = (const float*)d_in[15], *up4b1 = (const float*)d_in[16],
               * up4W2 = (const float*)d_in[17], *up4b2 = (const float*)d_in[18];
    const float* dn1W1 = (const float*)d_in[19], *dn1b1 = (const float*)d_in[20],
               * dn1W2 = (const float*)d_in[21], *dn1b2 = (const float*)d_in[22];
    const float* dn2W1 = (const float*)d_in[23], *dn2b1 = (const float*)d_in[24],
               * dn2W2 = (const float*)d_in[25], *dn2b2 = (const float*)d_in[26];
    const float* dn3W1 = (const float*)d_in[27], *dn3b1 = (const float*)d_in[28],
               * dn3W2 = (const float*)d_in[29], *dn3b2 = (const float*)d_in[30];

    float* out = (float*)d_out;

    float *H2, *H3, *H4, *HD3, *H3D, *HD2, *H2D, *HD1;
    cudaGetSymbolAddress((void**)&H2,  g_H2);
    cudaGetSymbolAddress((void**)&H3,  g_H3);
    cudaGetSymbolAddress((void**)&H4,  g_H4);
    cudaGetSymbolAddress((void**)&HD3, g_HD3);
    cudaGetSymbolAddress((void**)&H3D, g_H3D);
    cudaGetSymbolAddress((void**)&HD2, g_HD2);
    cudaGetSymbolAddress((void**)&H2D, g_H2D);
    cudaGetSymbolAddress((void**)&HD1, g_HD1);

    const size_t SMEM = (size_t)2 * BM * PITCH * sizeof(float);  // 135168 B
    cudaFuncSetAttribute(mlp_kernel<3>, cudaFuncAttributeMaxDynamicSharedMemorySize, (int)SMEM);
    cudaFuncSetAttribute(mlp_kernel<2>, cudaFuncAttributeMaxDynamicSharedMemorySize, (int)SMEM);

    // ---- upward pass ----
    mlp_kernel<3><<<N2 / BM, NTHR, SMEM>>>(h2, h1, idx2, up2W1, up2b1, up2W2, up2b2, H2);
    mlp_kernel<3><<<N3 / BM, NTHR, SMEM>>>(h3, H2, idx3, up3W1, up3b1, up3W2, up3b2, H3);
    mlp_kernel<3><<<N4 / BM, NTHR, SMEM>>>(h4, H3, idx4, up4W1, up4b1, up4W2, up4b2, H4);

    // ---- downward pass ----
    {
        long n4 = (long)N3 * 32;
        zero_kernel<<<(int)((n4 + 255) / 256), 256>>>((float4*)HD3, n4);
        long tot = (long)N4 * 32;
        scatter2_kernel<<<(int)((tot + 255) / 256), 256>>>(H4, idx4, HD3, N4);
        mlp_kernel<2><<<N3 / BM, NTHR, SMEM>>>(H3, HD3, nullptr, dn3W1, dn3b1, dn3W2, dn3b2, H3D);
    }
    {
        long n4 = (long)N2 * 32;
        zero_kernel<<<(int)((n4 + 255) / 256), 256>>>((float4*)HD2, n4);
        long tot = (long)N3 * 32;
        scatter2_kernel<<<(int)((tot + 255) / 256), 256>>>(H3D, idx3, HD2, N3);
        mlp_kernel<2><<<N2 / BM, NTHR, SMEM>>>(H2, HD2, nullptr, dn2W1, dn2b1, dn2W2, dn2b2, H2D);
    }
    {
        long n4 = (long)N1 * 32;
        zero_kernel<<<(int)((n4 + 255) / 256), 256>>>((float4*)HD1, n4);
        long tot = (long)N2 * 32;
        scatter2_kernel<<<(int)((tot + 255) / 256), 256>>>(H2D, idx2, HD1, N2);
        mlp_kernel<2><<<N1 / BM, NTHR, SMEM>>>(h1, HD1, nullptr, dn1W1, dn1b1, dn1W2, dn1b2, out);
    }
}